// round 1
// baseline (speedup 1.0000x reference)
#include <cuda_runtime.h>
#include <math.h>

// Problem constants (fixed shapes from reference)
#define BB    64
#define TMAX  256
#define PP    64
#define DD    128
#define CC    10
#define TBASE 367

// Scratch (no allocation allowed -> __device__ globals)
__device__ int   g_len[BB];
__device__ int   g_off[BB + 1];
__device__ float g_Z[TBASE * CC];     // Z[date][c] = table[date,:].W[c,:] + bias[c]
__device__ float g_Y[BB * CC * PP];   // Y[b][c][p] = x[b,p,:].W[c,:]

// ---------------------------------------------------------------------------
// K1: per-batch ragged lengths + exclusive prefix sum (tiny; 1 block)
// L_b = index of last nonzero date (numpy: tmax-1-argmax(rev nz); all-zero -> tmax-1)
// ---------------------------------------------------------------------------
__global__ void k_lengths(const int* __restrict__ dates) {
    int tid = threadIdx.x;
    if (tid < BB) {
        int L = TMAX - 1;
        const int* row = dates + (size_t)tid * TMAX;
        for (int t = TMAX - 1; t >= 0; --t) {
            if (row[t] != 0) { L = t; break; }
        }
        g_len[tid] = L;
    }
    __syncthreads();
    if (tid == 0) {
        int acc = 0;
        g_off[0] = 0;
        for (int b = 0; b < BB; ++b) { acc += g_len[b]; g_off[b + 1] = acc; }
    }
}

// ---------------------------------------------------------------------------
// K2: Z[pos][c] = sum_d sinusoid(pos,d) * W[c][d] + bias[c]
// sinusoid computed in double to match numpy float64 table, cast to f32.
// grid = TBASE blocks, 128 threads (one per d).
// ---------------------------------------------------------------------------
__global__ void k_Z(const float* __restrict__ W, const float* __restrict__ bias) {
    __shared__ float s[DD];
    int pos = blockIdx.x;
    int d   = threadIdx.x;

    int    j2  = d >> 1;
    double ex  = 2.0 * (double)j2 / (double)DD;
    double ang = (double)pos / pow((double)TBASE, ex);
    double v   = (d & 1) ? cos(ang) : sin(ang);
    float  tab = (float)v;

    for (int c = 0; c < CC; ++c) {
        s[d] = tab * W[c * DD + d];
        __syncthreads();
        for (int stride = DD / 2; stride > 0; stride >>= 1) {
            if (d < stride) s[d] += s[d + stride];
            __syncthreads();
        }
        if (d == 0) g_Z[pos * CC + c] = s[0] + bias[c];
        __syncthreads();
    }
}

// ---------------------------------------------------------------------------
// K3: Y[b][c][p] = dot(x[b,p,:], W[c,:])
// grid = BB blocks, 640 threads (c = tid/64, p = tid%64).
// x tile staged in shared with +1 padding (stride 129) to kill bank conflicts.
// ---------------------------------------------------------------------------
__global__ void k_Y(const float* __restrict__ x, const float* __restrict__ W) {
    __shared__ float xs[PP * (DD + 1)];   // 64 x 129 -> 33 KB
    __shared__ float Ws[CC * DD];         // 5 KB
    int b   = blockIdx.x;
    int tid = threadIdx.x;

    const float* xb = x + (size_t)b * PP * DD;
    for (int i = tid; i < PP * DD; i += blockDim.x) {
        int p = i / DD, d = i % DD;
        xs[p * (DD + 1) + d] = xb[i];
    }
    for (int i = tid; i < CC * DD; i += blockDim.x) Ws[i] = W[i];
    __syncthreads();

    int c = tid / PP;   // 0..9
    int p = tid % PP;   // 0..63
    const float* xr = &xs[p * (DD + 1)];
    const float* wr = &Ws[c * DD];
    float acc = 0.0f;
    #pragma unroll 8
    for (int d = 0; d < DD; ++d) acc = fmaf(xr[d], wr[d], acc);
    g_Y[b * (CC * PP) + tid] = acc;
}

// ---------------------------------------------------------------------------
// K4: masks (as float values in the tail of the output buffer)
// grid = BB blocks, 256 threads.
// ---------------------------------------------------------------------------
__global__ void k_masks(float* __restrict__ out, int N) {
    int b   = blockIdx.x;
    int off = g_off[b];
    int L   = g_len[b];
    float* m = out + (size_t)N * (CC * PP);
    for (int t = threadIdx.x; t < L; t += blockDim.x) {
        size_t base = (size_t)(off + t) * 2;
        m[base]     = (float)b;
        m[base + 1] = (float)t;
    }
}

// ---------------------------------------------------------------------------
// K5: recons[n][c][p] = Y[b][c][p] + Z[dates[b,t]][c]
// grid = N blocks, 640 threads. Token->(b,t) resolved by 64 parallel range
// tests against the offset table (one shared broadcast, no serial search).
// ---------------------------------------------------------------------------
__global__ void k_recons(float* __restrict__ out, const int* __restrict__ dates) {
    __shared__ int sb, st, sd;
    int n   = blockIdx.x;
    int tid = threadIdx.x;

    if (tid < BB) {
        int o0 = g_off[tid], o1 = g_off[tid + 1];
        if (n >= o0 && n < o1) {
            sb = tid;
            int t = n - o0;
            st = t;
            sd = dates[tid * TMAX + t];
        }
    }
    __syncthreads();

    int b = sb;
    int d = sd;
    int c = tid / PP;                          // uniform within half-warp groups
    float v = g_Y[b * (CC * PP) + tid] + g_Z[d * CC + c];
    out[(size_t)n * (CC * PP) + tid] = v;
    (void)st;
}

// ---------------------------------------------------------------------------
extern "C" void kernel_launch(void* const* d_in, const int* in_sizes, int n_in,
                              void* d_out, int out_size) {
    const float* x     = (const float*)d_in[0];
    /* d_in[1] = attentions, unused by the reference computation */
    const int*   dates = (const int*)  d_in[2];
    const float* W     = (const float*)d_in[3];
    const float* bias  = (const float*)d_in[4];
    float*       out   = (float*)d_out;

    // N tokens recovered from out_size: recons N*640 (+ masks N*2 if packed).
    int N;
    bool write_masks;
    if (out_size % (CC * PP + 2) == 0) {
        N = out_size / (CC * PP + 2);
        write_masks = true;
    } else {
        N = out_size / (CC * PP);
        write_masks = false;
    }

    k_lengths<<<1, 256>>>(dates);
    k_Z<<<TBASE, DD>>>(W, bias);
    k_Y<<<BB, CC * PP>>>(x, W);
    if (write_masks) k_masks<<<BB, 256>>>(out, N);
    k_recons<<<N, CC * PP>>>(out, dates);
}

// round 6
// speedup vs baseline: 1.5951x; 1.5951x over previous
#include <cuda_runtime.h>
#include <math.h>

// Problem constants (fixed shapes from reference)
#define BB    64
#define TMAX  256
#define PP    64
#define DD    128
#define CC    10
#define TBASE 367

#define ZPOS_PER_BLK 5
#define ZBLK ((TBASE + ZPOS_PER_BLK - 1) / ZPOS_PER_BLK)   // 74
#define PREP_GRID (BB + ZBLK + 1)                          // 139
#define CHUNKS 8                                           // output blocks per batch

// Scratch (no allocation allowed -> __device__ globals)
__device__ int   g_len[BB];
__device__ int   g_off[BB + 1];
__device__ float g_Z[TBASE * CC];     // Z[date][c] = table[date,:].W[c,:] + bias[c]
__device__ float g_Y[BB * CC * PP];   // Y[b][c][p] = x[b,p,:].W[c,:]

// ---------------------------------------------------------------------------
// K1 (prep): one wave, role-split by blockIdx.x
//   blocks [0, BB):          Y[b][c][p] = dot(x[b,p,:], W[c,:])
//   blocks [BB, BB+ZBLK):    Z[pos][c]  = dot(sinusoid(pos,:), W[c,:]) + bias[c]
//   block  BB+ZBLK:          ragged lengths + exclusive prefix sum
// blockDim = 640
// ---------------------------------------------------------------------------
__global__ void k_prep(const float* __restrict__ x,
                       const float* __restrict__ W,
                       const float* __restrict__ bias,
                       const int*   __restrict__ dates) {
    __shared__ float Ws[CC * DD];                 // 5 KB (Y and Z branches both use)
    int blk = blockIdx.x;
    int tid = threadIdx.x;

    if (blk < BB) {
        // ---- Y branch ----
        __shared__ float xs[PP * (DD + 1)];       // 33 KB, +1 pad kills conflicts
        const float* xb = x + (size_t)blk * PP * DD;
        for (int i = tid; i < PP * DD; i += blockDim.x) {
            int p = i / DD, d = i % DD;
            xs[p * (DD + 1) + d] = xb[i];
        }
        for (int i = tid; i < CC * DD; i += blockDim.x) Ws[i] = W[i];
        __syncthreads();

        int c = tid / PP;   // 0..9
        int p = tid % PP;   // 0..63
        const float* xr = &xs[p * (DD + 1)];
        const float* wr = &Ws[c * DD];
        float acc = 0.0f;
        #pragma unroll 8
        for (int d = 0; d < DD; ++d) acc = fmaf(xr[d], wr[d], acc);
        g_Y[blk * (CC * PP) + tid] = acc;

    } else if (blk < BB + ZBLK) {
        // ---- Z branch ----
        __shared__ float stab[ZPOS_PER_BLK * DD];  // 2.5 KB
        int zb   = blk - BB;
        int posL = tid / DD;                       // 0..4
        int d    = tid % DD;
        int pos  = zb * ZPOS_PER_BLK + posL;

        if (pos < TBASE && tid < ZPOS_PER_BLK * DD) {
            // angle in double, range-reduce, evaluate sin/cos in float
            int    j2   = d >> 1;
            double ex   = (double)j2 * (2.0 / (double)DD);
            double invf = exp(-ex * log((double)TBASE));
            double ang  = (double)pos * invf;
            const double TWO_PI = 6.283185307179586476925287;
            double q  = (double)__double2int_rn(ang * (1.0 / TWO_PI));
            double r  = ang - q * TWO_PI;
            float  rf = (float)r;
            float  tab = (d & 1) ? cosf(rf) : sinf(rf);
            stab[posL * DD + d] = tab;
        }
        for (int i = tid; i < CC * DD; i += blockDim.x) Ws[i] = W[i];
        __syncthreads();

        if (tid < ZPOS_PER_BLK * CC) {             // 50 active threads
            int pL  = tid / CC;
            int c   = tid % CC;
            int pos2 = zb * ZPOS_PER_BLK + pL;
            if (pos2 < TBASE) {
                const float* tr = &stab[pL * DD];
                const float* wr = &Ws[c * DD];
                float acc = 0.0f;
                #pragma unroll 8
                for (int d2 = 0; d2 < DD; ++d2) acc = fmaf(tr[d2], wr[d2], acc);
                g_Z[pos2 * CC + c] = acc + bias[c];
            }
        }

    } else {
        // ---- lengths + prefix branch ----
        if (tid < BB) {
            int L = TMAX - 1;                      // all-zero row -> TMAX-1 (numpy argmax semantics)
            const int* row = dates + (size_t)tid * TMAX;
            for (int t = TMAX - 1; t >= 0; --t) {
                if (row[t] != 0) { L = t; break; }
            }
            g_len[tid] = L;
        }
        __syncthreads();
        if (tid == 0) {
            int acc = 0;
            g_off[0] = 0;
            for (int b = 0; b < BB; ++b) { acc += g_len[b]; g_off[b + 1] = acc; }
        }
    }
}

// ---------------------------------------------------------------------------
// K2 (output): recons + masks fused. grid = BB*CHUNKS blocks, 256 threads.
// Block = (batch b, chunk of its tokens). Y[b] staged in shared once; the
// chunk's dates slice staged with one coalesced pass. One warp per token:
// 5 x float4 stores (512B contiguous per warp step).
// ---------------------------------------------------------------------------
__global__ void __launch_bounds__(256) k_out(float* __restrict__ out,
                                             const int* __restrict__ dates,
                                             int N, int write_masks) {
    __shared__ float4 Ys[CC * PP / 4];            // 160 float4 = 2.5 KB
    __shared__ int    sdates[(TMAX + CHUNKS - 1) / CHUNKS + 1];  // chunk's date slice
    int b     = blockIdx.x / CHUNKS;
    int chunk = blockIdx.x % CHUNKS;
    int tid   = threadIdx.x;

    const float4* Yb = (const float4*)(g_Y + (size_t)b * (CC * PP));
    if (tid < CC * PP / 4) Ys[tid] = Yb[tid];

    int off  = g_off[b];
    int L    = g_len[b];
    int clen = (L + CHUNKS - 1) / CHUNKS;
    int t0   = chunk * clen;
    int t1   = min(L, t0 + clen);
    int nt   = t1 - t0;                            // tokens in this chunk (<= 32)

    if (tid < nt) sdates[tid] = dates[b * TMAX + t0 + tid];
    __syncthreads();

    int w    = tid >> 5;
    int lane = tid & 31;
    float* mbase = out + (size_t)N * (CC * PP);

    for (int ti = w; ti < nt; ti += 8) {
        int t = t0 + ti;
        int d = sdates[ti];
        int n = off + t;
        const float* Zrow = g_Z + d * CC;
        float4* o = (float4*)(out + (size_t)n * (CC * PP));
        #pragma unroll
        for (int i = 0; i < 5; ++i) {
            int v = lane + i * 32;
            int c = v >> 4;
            float  z = __ldg(&Zrow[c]);
            float4 y = Ys[v];
            y.x += z; y.y += z; y.z += z; y.w += z;
            o[v] = y;
        }
        if (write_masks && lane == 0) {
            float2 m = make_float2((float)b, (float)t);
            *(float2*)(mbase + 2 * (size_t)n) = m;
        }
    }
}

// ---------------------------------------------------------------------------
extern "C" void kernel_launch(void* const* d_in, const int* in_sizes, int n_in,
                              void* d_out, int out_size) {
    const float* x     = (const float*)d_in[0];
    /* d_in[1] = attentions, unused by the reference computation */
    const int*   dates = (const int*)  d_in[2];
    const float* W     = (const float*)d_in[3];
    const float* bias  = (const float*)d_in[4];
    float*       out   = (float*)d_out;

    // N tokens recovered from out_size: recons N*640 (+ masks N*2 if packed).
    int N;
    int write_masks;
    if (out_size % (CC * PP + 2) == 0) {
        N = out_size / (CC * PP + 2);
        write_masks = 1;
    } else {
        N = out_size / (CC * PP);
        write_masks = 0;
    }

    k_prep<<<PREP_GRID, CC * PP>>>(x, W, bias, dates);
    k_out<<<BB * CHUNKS, 256>>>(out, dates, N, write_masks);
}

// round 7
// speedup vs baseline: 1.9076x; 1.1959x over previous
#include <cuda_runtime.h>
#include <math.h>

// Problem constants (fixed shapes from reference)
#define BB    64
#define TMAX  256
#define PP    64
#define DD    128
#define CC    10
#define TBASE 367

#define ZPOS_PER_BLK 5
#define ZBLK ((TBASE + ZPOS_PER_BLK - 1) / ZPOS_PER_BLK)   // 74
#define PREP_GRID (BB + ZBLK + 1)                          // 139
#define VPT (CC * PP / 4)                                  // 160 float4 per token

// Scratch (no allocation allowed -> __device__ globals)
__device__ int   g_len[BB];
__device__ int   g_off[BB + 1];
__device__ int   g_info[BB * TMAX];   // per-token packed: date[0:9) | t[9:17) | b[17:23)
__device__ float g_Z[TBASE * CC];     // Z[date][c] = table[date,:].W[c,:] + bias[c]
__device__ float g_Y[BB * CC * PP];   // Y[b][c][p] = x[b,p,:].W[c,:]

// ---------------------------------------------------------------------------
// K1 (prep): one wave, role-split by blockIdx.x
//   blocks [0, BB):          Y[b][c][p] = dot(x[b,p,:], W[c,:])
//   blocks [BB, BB+ZBLK):    Z[pos][c]  = dot(sinusoid(pos,:), W[c,:]) + bias[c]
//   block  BB+ZBLK:          ragged lengths + prefix sum + token info table
// blockDim = 640
// ---------------------------------------------------------------------------
__global__ void k_prep(const float* __restrict__ x,
                       const float* __restrict__ W,
                       const float* __restrict__ bias,
                       const int*   __restrict__ dates) {
    __shared__ float Ws[CC * DD];                 // 5 KB (Y and Z branches both use)
    int blk = blockIdx.x;
    int tid = threadIdx.x;

    if (blk < BB) {
        // ---- Y branch ----
        __shared__ float xs[PP * (DD + 1)];       // 33 KB, +1 pad kills conflicts
        const float* xb = x + (size_t)blk * PP * DD;
        for (int i = tid; i < PP * DD; i += blockDim.x) {
            int p = i / DD, d = i % DD;
            xs[p * (DD + 1) + d] = xb[i];
        }
        for (int i = tid; i < CC * DD; i += blockDim.x) Ws[i] = W[i];
        __syncthreads();

        int c = tid / PP;   // 0..9
        int p = tid % PP;   // 0..63
        const float* xr = &xs[p * (DD + 1)];
        const float* wr = &Ws[c * DD];
        float acc = 0.0f;
        #pragma unroll 8
        for (int d = 0; d < DD; ++d) acc = fmaf(xr[d], wr[d], acc);
        g_Y[blk * (CC * PP) + tid] = acc;

    } else if (blk < BB + ZBLK) {
        // ---- Z branch ----
        __shared__ float  stab[ZPOS_PER_BLK * DD]; // 2.5 KB
        __shared__ double s_invf[DD / 2];          // 64 distinct inverse freqs
        int zb = blk - BB;

        // Only 64 distinct j2 values -> 64 double exps per block (was 640).
        if (tid < DD / 2) {
            const double LOG_TBASE = 5.905362160890256;   // ln(367)
            double ex = (double)tid * (2.0 / (double)DD);
            s_invf[tid] = exp(-ex * LOG_TBASE);
        }
        for (int i = tid; i < CC * DD; i += blockDim.x) Ws[i] = W[i];
        __syncthreads();

        int posL = tid / DD;                       // 0..4
        int d    = tid % DD;
        int pos  = zb * ZPOS_PER_BLK + posL;
        if (pos < TBASE && tid < ZPOS_PER_BLK * DD) {
            double ang = (double)pos * s_invf[d >> 1];
            const double TWO_PI = 6.283185307179586476925287;
            double q  = (double)__double2int_rn(ang * (1.0 / TWO_PI));
            float  rf = (float)(ang - q * TWO_PI);
            stab[posL * DD + d] = (d & 1) ? cosf(rf) : sinf(rf);
        }
        __syncthreads();

        if (tid < ZPOS_PER_BLK * CC) {             // 50 active threads
            int pL   = tid / CC;
            int c    = tid % CC;
            int pos2 = zb * ZPOS_PER_BLK + pL;
            if (pos2 < TBASE) {
                const float* tr = &stab[pL * DD];
                const float* wr = &Ws[c * DD];
                float acc = 0.0f;
                #pragma unroll 8
                for (int d2 = 0; d2 < DD; ++d2) acc = fmaf(tr[d2], wr[d2], acc);
                g_Z[pos2 * CC + c] = acc + bias[c];
            }
        }

    } else {
        // ---- lengths + prefix + token-info branch ----
        if (tid < BB) {
            int L = TMAX - 1;                      // all-zero row -> TMAX-1 (numpy argmax semantics)
            const int* row = dates + (size_t)tid * TMAX;
            for (int t = TMAX - 1; t >= 0; --t) {
                if (row[t] != 0) { L = t; break; }
            }
            g_len[tid] = L;
        }
        __syncthreads();
        __shared__ int soff[BB + 1];
        if (tid == 0) {
            int acc = 0;
            soff[0] = 0;
            g_off[0] = 0;
            for (int b = 0; b < BB; ++b) {
                acc += g_len[b];
                soff[b + 1] = acc;
                g_off[b + 1] = acc;
            }
        }
        __syncthreads();
        for (int b = 0; b < BB; ++b) {
            int base = soff[b];
            int L    = soff[b + 1] - base;
            for (int t = tid; t < L; t += blockDim.x) {
                int dte = dates[b * TMAX + t];
                g_info[base + t] = dte | (t << 9) | (b << 17);
            }
        }
    }
}

// ---------------------------------------------------------------------------
// K2 (output): flat, one thread per output float4. 160 float4 per token and
// 160 = 5*32, so every warp lives inside one token: uniform info load,
// 512B coalesced Y read + 512B coalesced store per warp. No smem, no syncs.
// ---------------------------------------------------------------------------
__global__ void __launch_bounds__(256) k_out(float* __restrict__ out,
                                             int N, int write_masks) {
    int idx = blockIdx.x * 256 + threadIdx.x;
    int total = N * VPT;
    if (idx >= total) return;

    unsigned un = (unsigned)idx / VPT;   // token index (const-div -> mulhi)
    int n = (int)un;
    int v = idx - n * VPT;               // float4 index within token, 0..159

    int info = __ldg(&g_info[n]);        // uniform within the warp
    int d = info & 511;
    int b = info >> 17;
    int c = v >> 4;                      // channel = (v*4)/64

    float4 y = __ldg((const float4*)g_Y + b * VPT + v);
    float  z = g_Z[d * CC + c];
    y.x += z; y.y += z; y.z += z; y.w += z;
    ((float4*)out)[idx] = y;

    if (write_masks && v == 0) {
        int t = (info >> 9) & 255;
        float2 m = make_float2((float)b, (float)t);
        *(float2*)(out + (size_t)N * (CC * PP) + 2 * (size_t)n) = m;
    }
}

// ---------------------------------------------------------------------------
extern "C" void kernel_launch(void* const* d_in, const int* in_sizes, int n_in,
                              void* d_out, int out_size) {
    const float* x     = (const float*)d_in[0];
    /* d_in[1] = attentions, unused by the reference computation */
    const int*   dates = (const int*)  d_in[2];
    const float* W     = (const float*)d_in[3];
    const float* bias  = (const float*)d_in[4];
    float*       out   = (float*)d_out;

    // N tokens recovered from out_size: recons N*640 (+ masks N*2 if packed).
    int N;
    int write_masks;
    if (out_size % (CC * PP + 2) == 0) {
        N = out_size / (CC * PP + 2);
        write_masks = 1;
    } else {
        N = out_size / (CC * PP);
        write_masks = 0;
    }

    k_prep<<<PREP_GRID, CC * PP>>>(x, W, bias, dates);
    int total = N * VPT;
    k_out<<<(total + 255) / 256, 256>>>(out, N, write_masks);
}